// round 11
// baseline (speedup 1.0000x reference)
#include <cuda_runtime.h>
#include <cstdint>

#define NN 8192
#define KK 64
#define DD 256
#define HH 128
#define K1_BLOCKS   128
#define K1_THREADS  512

// ---- flat fp32 output layout (concat of reference tuple) ----
#define OFF_ADJ    0LL
#define OFF_FEAT   ((long long)NN * NN)
#define OFF_PROB   (OFF_FEAT + (long long)NN * DD)
#define OFF_PAIR   (OFF_PROB + (long long)NN * KK * 2)
#define OFF_BEFORE (OFF_PAIR + (long long)NN * KK * 2)
#define OFF_AFTER  (OFF_BEFORE + 1)
#define OFF_LEFT   (OFF_AFTER + 1)

// scratch: featW = feat @ W1 [N,128] (4 MB, L2-resident for the edge gather)
__device__ float  g_featW[(size_t)NN * HH];
// scratch: per-row kept edges (col bits, normalized value), 32 per row (2 MB)
__device__ float2 g_kept[(size_t)NN * 32];

// ---------------------------------------------------------------------------
// Kernel 1: PURE GEMM featW = feat @ W1 (+16MB feat copy, scalar inits).
// No adj fill here — the 256MB zero-fill runs as a concurrent memset branch.
// W1 staged in 128KB smem, 16 warps x 4 rows, single FMA pass (R8 core).
// ---------------------------------------------------------------------------
extern __shared__ float k1_smem[];

__global__ void __launch_bounds__(K1_THREADS) featw_kernel(const float* __restrict__ feat,
                                                           const float* __restrict__ W1,
                                                           float* __restrict__ out) {
    float* sW   = k1_smem;                  // 256*128 floats = 128 KB
    float* srow = k1_smem + DD * HH;        // 16 warps * 4 rows * 256 = 64 KB

    const int tid  = threadIdx.x;
    const int warp = tid >> 5;
    const int lane = tid & 31;

    // stage full W1: 8192 float4, 16 per thread, coalesced
    {
        const float4* W14 = reinterpret_cast<const float4*>(W1);
        float4* sW4 = reinterpret_cast<float4*>(sW);
#pragma unroll
        for (int i = 0; i < 16; i++)
            sW4[i * K1_THREADS + tid] = W14[i * K1_THREADS + tid];
    }

    // load this warp's 4 feat rows -> smem (+ streaming copy to out)
    const int row0 = blockIdx.x * 64 + warp * 4;
    float* rbase = srow + warp * 4 * DD;
#pragma unroll
    for (int r = 0; r < 4; r++) {
        const float4* f4 = reinterpret_cast<const float4*>(feat + (size_t)(row0 + r) * DD);
        float4 x0 = __ldcs(&f4[lane]), x1 = __ldcs(&f4[lane + 32]);
        reinterpret_cast<float4*>(rbase + r * DD)[lane]      = x0;
        reinterpret_cast<float4*>(rbase + r * DD)[lane + 32] = x1;
        float4* oc = reinterpret_cast<float4*>(out + OFF_FEAT + (size_t)(row0 + r) * DD);
        __stcs(&oc[lane], x0); __stcs(&oc[lane + 32], x1);
    }
    __syncthreads();   // W1 staged + rows written

    const float4* sW4 = reinterpret_cast<const float4*>(sW);
    const float* r0 = rbase;
    const float* r1 = rbase + DD;
    const float* r2 = rbase + 2 * DD;
    const float* r3 = rbase + 3 * DD;

    float4 acc0 = make_float4(0.f, 0.f, 0.f, 0.f);
    float4 acc1 = make_float4(0.f, 0.f, 0.f, 0.f);
    float4 acc2 = make_float4(0.f, 0.f, 0.f, 0.f);
    float4 acc3 = make_float4(0.f, 0.f, 0.f, 0.f);
#pragma unroll 4
    for (int k = 0; k < DD; k++) {
        float4 wv = sW4[k * 32 + lane];
        float s0 = r0[k], s1 = r1[k], s2 = r2[k], s3 = r3[k];
        acc0.x = fmaf(s0, wv.x, acc0.x); acc0.y = fmaf(s0, wv.y, acc0.y);
        acc0.z = fmaf(s0, wv.z, acc0.z); acc0.w = fmaf(s0, wv.w, acc0.w);
        acc1.x = fmaf(s1, wv.x, acc1.x); acc1.y = fmaf(s1, wv.y, acc1.y);
        acc1.z = fmaf(s1, wv.z, acc1.z); acc1.w = fmaf(s1, wv.w, acc1.w);
        acc2.x = fmaf(s2, wv.x, acc2.x); acc2.y = fmaf(s2, wv.y, acc2.y);
        acc2.z = fmaf(s2, wv.z, acc2.z); acc2.w = fmaf(s2, wv.w, acc2.w);
        acc3.x = fmaf(s3, wv.x, acc3.x); acc3.y = fmaf(s3, wv.y, acc3.y);
        acc3.z = fmaf(s3, wv.z, acc3.z); acc3.w = fmaf(s3, wv.w, acc3.w);
    }
    reinterpret_cast<float4*>(g_featW + (size_t)(row0 + 0) * HH)[lane] = acc0;
    reinterpret_cast<float4*>(g_featW + (size_t)(row0 + 1) * HH)[lane] = acc1;
    reinterpret_cast<float4*>(g_featW + (size_t)(row0 + 2) * HH)[lane] = acc2;
    reinterpret_cast<float4*>(g_featW + (size_t)(row0 + 3) * HH)[lane] = acc3;

    if (blockIdx.x == 0 && tid == 0) {
        out[OFF_BEFORE] = 64.0f;
        out[OFF_AFTER]  = 0.0f;
    }
}

// ---------------------------------------------------------------------------
// Kernel 2: edge compute (WARP-PER-ROW, R9 core, NO fill, NO adj scatter).
// Writes prob/pair/left_row/after and the kept (col, normalized val) pairs
// into g_kept for the post-memset scatter kernel.
// ---------------------------------------------------------------------------
__global__ void __launch_bounds__(256) edge_kernel(const float* __restrict__ adj,
                                                   const int*   __restrict__ nbr,
                                                   const float* __restrict__ b1,
                                                   const float* __restrict__ prelu_a,
                                                   const float* __restrict__ W2,
                                                   const float* __restrict__ b2,
                                                   float* __restrict__ out) {
    __shared__ int   snbr[8][KK];
    __shared__ __align__(16) float sD[8][KK];   // D values, then reused as p1

    const int tid  = threadIdx.x;
    const int warp = tid >> 5;
    const int lane = tid & 31;
    const int row  = blockIdx.x * 8 + warp;

    const int nlo = __ldg(&nbr[row * KK + lane]);
    const int nhi = __ldg(&nbr[row * KK + lane + 32]);
    snbr[warp][lane]      = nlo;
    snbr[warp][lane + 32] = nhi;
    const float vlo = __ldcs(adj + (size_t)row * NN + nlo);
    const float vhi = __ldcs(adj + (size_t)row * NN + nhi);

    const float4* fW4 = reinterpret_cast<const float4*>(g_featW);
    float4 fs = fW4[(size_t)row * 32 + lane];
    {
        float4 bb = __ldg(&reinterpret_cast<const float4*>(b1)[lane]);
        fs.x += bb.x; fs.y += bb.y; fs.z += bb.z; fs.w += bb.w;
    }

    // pair_list (independent)
    {
        float2* pp = reinterpret_cast<float2*>(out + OFF_PAIR) + (long long)row * KK;
        __stcs(&pp[lane],      make_float2((float)row, (float)nlo));
        __stcs(&pp[lane + 32], make_float2((float)row, (float)nhi));
    }

    const int j0 = lane * 4;
    const float a0 = __ldg(&prelu_a[j0 + 0]), a1 = __ldg(&prelu_a[j0 + 1]),
                a2 = __ldg(&prelu_a[j0 + 2]), a3 = __ldg(&prelu_a[j0 + 3]);
    const float wd0 = __ldg(&W2[(j0 + 0) * 2 + 1]) - __ldg(&W2[(j0 + 0) * 2]);
    const float wd1 = __ldg(&W2[(j0 + 1) * 2 + 1]) - __ldg(&W2[(j0 + 1) * 2]);
    const float wd2 = __ldg(&W2[(j0 + 2) * 2 + 1]) - __ldg(&W2[(j0 + 2) * 2]);
    const float wd3 = __ldg(&W2[(j0 + 3) * 2 + 1]) - __ldg(&W2[(j0 + 3) * 2]);
    const float b2d = __ldg(&b2[1]) - __ldg(&b2[0]);

    const bool h16 = (lane & 16) != 0;
    const bool h8  = (lane & 8)  != 0;
    const bool h4  = (lane & 4)  != 0;
    const int  eidx = ((lane >> 2) & 1) * 4 + ((lane >> 3) & 1) * 2 + ((lane >> 4) & 1);
    const bool writer = (lane & 3) == 0;

    __syncwarp();   // snbr visible

#pragma unroll
    for (int b = 0; b < 8; b++) {          // 8 batches of 8 edges, 8-deep gather
        float4 fd[8];
#pragma unroll
        for (int e = 0; e < 8; e++)
            fd[e] = fW4[(size_t)snbr[warp][b * 8 + e] * 32 + lane];

        float dd[8];
#pragma unroll
        for (int e = 0; e < 8; e++) {
            float h0 = fs.x - fd[e].x, h1 = fs.y - fd[e].y;
            float h2 = fs.z - fd[e].z, h3 = fs.w - fd[e].w;
            h0 = (h0 >= 0.f) ? h0 : a0 * h0;
            h1 = (h1 >= 0.f) ? h1 : a1 * h1;
            h2 = (h2 >= 0.f) ? h2 : a2 * h2;
            h3 = (h3 >= 0.f) ? h3 : a3 * h3;
            dd[e] = h0 * wd0 + h1 * wd1 + h2 * wd2 + h3 * wd3;
        }

        // selection multi-reduce (same summation tree as butterfly)
        float w[4];
#pragma unroll
        for (int i = 0; i < 4; i++) {
            float send = h16 ? dd[2 * i] : dd[2 * i + 1];
            float recv = __shfl_xor_sync(0xffffffffu, send, 16);
            w[i] = (h16 ? dd[2 * i + 1] : dd[2 * i]) + recv;
        }
        float x0, x1;
        {
            float send = h8 ? w[0] : w[1];
            float recv = __shfl_xor_sync(0xffffffffu, send, 8);
            x0 = (h8 ? w[1] : w[0]) + recv;
            send = h8 ? w[2] : w[3];
            recv = __shfl_xor_sync(0xffffffffu, send, 8);
            x1 = (h8 ? w[3] : w[2]) + recv;
        }
        float y;
        {
            float send = h4 ? x0 : x1;
            float recv = __shfl_xor_sync(0xffffffffu, send, 4);
            y = (h4 ? x1 : x0) + recv;
        }
        y += __shfl_xor_sync(0xffffffffu, y, 2);
        y += __shfl_xor_sync(0xffffffffu, y, 1);

        if (writer) sD[warp][b * 8 + eidx] = y;
    }
    __syncwarp();

    // sigmoid probs (p0 = sigmoid(-D) = e * p1)
    const float D_lo = sD[warp][lane]      + b2d;
    const float D_hi = sD[warp][lane + 32] + b2d;
    const float e_lo = expf(-D_lo), e_hi = expf(-D_hi);
    const float p1_lo = 1.0f / (1.0f + e_lo);
    const float p1_hi = 1.0f / (1.0f + e_hi);
    const float p0_lo = e_lo * p1_lo;
    const float p0_hi = e_hi * p1_hi;
    {
        float2* pr = reinterpret_cast<float2*>(out + OFF_PROB) + (long long)row * KK;
        __stcs(&pr[lane],      make_float2(p0_lo, p1_lo));
        __stcs(&pr[lane + 32], make_float2(p0_hi, p1_hi));
    }
    sD[warp][lane]      = p1_lo;    // reuse as sp1 (own-slot rewrite, safe)
    sD[warp][lane + 32] = p1_hi;
    __syncwarp();

    // stable ascending rank, vectorized (16 x LDS.128)
    int rank_lo = 0, rank_hi = 0;
    const float4* sp4 = reinterpret_cast<const float4*>(&sD[warp][0]);
#pragma unroll
    for (int q = 0; q < 16; q++) {
        float4 v = sp4[q];
        const int j = q * 4;
        rank_lo += (v.x < p1_lo) || (v.x == p1_lo && (j + 0) < lane);
        rank_lo += (v.y < p1_lo) || (v.y == p1_lo && (j + 1) < lane);
        rank_lo += (v.z < p1_lo) || (v.z == p1_lo && (j + 2) < lane);
        rank_lo += (v.w < p1_lo) || (v.w == p1_lo && (j + 3) < lane);
        rank_hi += (v.x < p1_hi) || (v.x == p1_hi && (j + 0) < lane + 32);
        rank_hi += (v.y < p1_hi) || (v.y == p1_hi && (j + 1) < lane + 32);
        rank_hi += (v.z < p1_hi) || (v.z == p1_hi && (j + 2) < lane + 32);
        rank_hi += (v.w < p1_hi) || (v.w == p1_hi && (j + 3) < lane + 32);
    }
    const int keep_lo = rank_lo >= 32;
    const int keep_hi = rank_hi >= 32;

    if (keep_lo)
        __stcs(&out[OFF_LEFT + (long long)row * 32 + (rank_lo - 32)],
               (float)(row * KK + lane));
    if (keep_hi)
        __stcs(&out[OFF_LEFT + (long long)row * 32 + (rank_hi - 32)],
               (float)(row * KK + lane + 32));

    // degree + nonzero-kept count
    float v = (keep_lo ? vlo : 0.f) + (keep_hi ? vhi : 0.f);
    float c = (keep_lo && vlo != 0.f ? 1.f : 0.f) + (keep_hi && vhi != 0.f ? 1.f : 0.f);
#pragma unroll
    for (int off = 16; off; off >>= 1) {
        v += __shfl_xor_sync(0xffffffffu, v, off);
        c += __shfl_xor_sync(0xffffffffu, c, off);
    }
    if (lane == 0) atomicAdd(out + OFF_AFTER, c * (1.0f / 8192.0f));

    // stash kept (col, normalized value) pairs for the scatter kernel
    const float inv = 1.0f / (v + 1e-6f);
    if (keep_lo)
        g_kept[(size_t)row * 32 + (rank_lo - 32)] =
            make_float2(__int_as_float(nlo), vlo * inv);
    if (keep_hi)
        g_kept[(size_t)row * 32 + (rank_hi - 32)] =
            make_float2(__int_as_float(nhi), vhi * inv);
}

// ---------------------------------------------------------------------------
// Kernel 3: scatter the 262144 kept values into the memset-zeroed adj.
// Coalesced 8B reads, scattered 4B writes; ~1MB of stores total.
// ---------------------------------------------------------------------------
__global__ void __launch_bounds__(256) scatter_kernel(float* __restrict__ out) {
    const int i   = blockIdx.x * 256 + threadIdx.x;   // 0 .. 262143
    const int row = i >> 5;
    float2 kv = g_kept[i];
    const int col = __float_as_int(kv.x);
    out[(size_t)row * NN + col] = kv.y;
}

// ---------------------------------------------------------------------------
extern "C" void kernel_launch(void* const* d_in, const int* in_sizes, int n_in,
                              void* d_out, int out_size) {
    const float* adj = nullptr; const float* feat = nullptr;
    const int*   nbr = nullptr; const float* W1   = nullptr;
    const float* b1  = nullptr; const float* pa   = nullptr;
    const float* W2  = nullptr; const float* b2   = nullptr;

    for (int i = 0; i < n_in; i++) {
        long long s = in_sizes[i];
        if      (s == (long long)NN * NN) adj  = (const float*)d_in[i];
        else if (s == (long long)NN * DD) feat = (const float*)d_in[i];
        else if (s == (long long)NN * KK) nbr  = (const int*)d_in[i];
        else if (s == (long long)DD * HH) W1   = (const float*)d_in[i];
        else if (s == HH) { if (!b1) b1 = (const float*)d_in[i];
                            else     pa = (const float*)d_in[i]; }
        else if (s == HH * 2) W2 = (const float*)d_in[i];
        else if (s == 2)      b2 = (const float*)d_in[i];
    }

    float* out = (float*)d_out;

    static cudaStream_t s2 = nullptr;
    static cudaEvent_t  e0 = nullptr, e1 = nullptr;
    static int k1_smem_bytes = 0;
    if (!s2) {
        cudaStreamCreateWithFlags(&s2, cudaStreamNonBlocking);
        cudaEventCreateWithFlags(&e0, cudaEventDisableTiming);
        cudaEventCreateWithFlags(&e1, cudaEventDisableTiming);
        k1_smem_bytes = (DD * HH + 16 * 4 * DD) * (int)sizeof(float);   // 192 KB
        cudaFuncSetAttribute(featw_kernel,
                             cudaFuncAttributeMaxDynamicSharedMemorySize, k1_smem_bytes);
    }

    // fork: 256MB adj zero-fill runs concurrently with GEMM + edge compute
    cudaEventRecord(e0, 0);
    cudaStreamWaitEvent(s2, e0, 0);
    cudaMemsetAsync(out, 0, (size_t)NN * NN * sizeof(float), s2);
    cudaEventRecord(e1, s2);

    featw_kernel<<<K1_BLOCKS, K1_THREADS, k1_smem_bytes>>>(feat, W1, out);
    edge_kernel<<<NN / 8, 256>>>(adj, nbr, b1, pa, W2, b2, out);

    // join: scatter must land on the zeroed adj
    cudaStreamWaitEvent(0, e1, 0);
    scatter_kernel<<<NN * 32 / 256, 256>>>(out);
}

// round 12
// speedup vs baseline: 1.1230x; 1.1230x over previous
#include <cuda_runtime.h>

#define NN 8192
#define KK 64
#define DD 256
#define HH 128
#define K1_BLOCKS   128
#define K1_THREADS  512
#define K1_FILLROWS 3072   // rows [0,3072) filled by k1 (24 rows/block, 96 MB)

// ---- flat fp32 output layout (concat of reference tuple) ----
#define OFF_ADJ    0LL
#define OFF_FEAT   ((long long)NN * NN)
#define OFF_PROB   (OFF_FEAT + (long long)NN * DD)
#define OFF_PAIR   (OFF_PROB + (long long)NN * KK * 2)
#define OFF_BEFORE (OFF_PAIR + (long long)NN * KK * 2)
#define OFF_AFTER  (OFF_BEFORE + 1)
#define OFF_LEFT   (OFF_AFTER + 1)

// scratch: featW = feat @ W1   [N, 128]  (4 MB, L2-resident for edge gather)
__device__ float g_featW[(size_t)NN * HH];

// ---------------------------------------------------------------------------
// Kernel 1 (R8-identical, measured 32us): featW = feat @ W1 with the 96MB
// zero-fill software-pipelined into the FMA loop (1 STG.128 every other
// k-iter drains in the FMA latency shadow). W1 staged in 128KB smem.
// ---------------------------------------------------------------------------
extern __shared__ float k1_smem[];

__global__ void __launch_bounds__(K1_THREADS) featw_kernel(const float* __restrict__ feat,
                                                           const float* __restrict__ W1,
                                                           float* __restrict__ out) {
    float* sW   = k1_smem;                  // 256*128 floats = 128 KB
    float* srow = k1_smem + DD * HH;        // 16 warps * 4 rows * 256 = 64 KB

    const int tid  = threadIdx.x;
    const int warp = tid >> 5;
    const int lane = tid & 31;

    {
        const float4* W14 = reinterpret_cast<const float4*>(W1);
        float4* sW4 = reinterpret_cast<float4*>(sW);
#pragma unroll
        for (int i = 0; i < 16; i++)
            sW4[i * K1_THREADS + tid] = W14[i * K1_THREADS + tid];
    }

    const int row0 = blockIdx.x * 64 + warp * 4;
    float* rbase = srow + warp * 4 * DD;
#pragma unroll
    for (int r = 0; r < 4; r++) {
        const float4* f4 = reinterpret_cast<const float4*>(feat + (size_t)(row0 + r) * DD);
        float4 x0 = __ldcs(&f4[lane]), x1 = __ldcs(&f4[lane + 32]);
        reinterpret_cast<float4*>(rbase + r * DD)[lane]      = x0;
        reinterpret_cast<float4*>(rbase + r * DD)[lane + 32] = x1;
        float4* oc = reinterpret_cast<float4*>(out + OFF_FEAT + (size_t)(row0 + r) * DD);
        __stcs(&oc[lane], x0); __stcs(&oc[lane + 32], x1);
    }
    __syncthreads();

    const float4* sW4 = reinterpret_cast<const float4*>(sW);
    const float* r0 = rbase;
    const float* r1 = rbase + DD;
    const float* r2 = rbase + 2 * DD;
    const float* r3 = rbase + 3 * DD;

    float4* fdst = reinterpret_cast<float4*>(
        out + (size_t)blockIdx.x * (K1_FILLROWS / K1_BLOCKS) * NN);
    const float4 z = make_float4(0.f, 0.f, 0.f, 0.f);

    float4 acc0 = make_float4(0.f, 0.f, 0.f, 0.f);
    float4 acc1 = make_float4(0.f, 0.f, 0.f, 0.f);
    float4 acc2 = make_float4(0.f, 0.f, 0.f, 0.f);
    float4 acc3 = make_float4(0.f, 0.f, 0.f, 0.f);
#pragma unroll 4
    for (int k = 0; k < DD; k++) {
        float4 wv = sW4[k * 32 + lane];
        float s0 = r0[k], s1 = r1[k], s2 = r2[k], s3 = r3[k];
        acc0.x = fmaf(s0, wv.x, acc0.x); acc0.y = fmaf(s0, wv.y, acc0.y);
        acc0.z = fmaf(s0, wv.z, acc0.z); acc0.w = fmaf(s0, wv.w, acc0.w);
        acc1.x = fmaf(s1, wv.x, acc1.x); acc1.y = fmaf(s1, wv.y, acc1.y);
        acc1.z = fmaf(s1, wv.z, acc1.z); acc1.w = fmaf(s1, wv.w, acc1.w);
        acc2.x = fmaf(s2, wv.x, acc2.x); acc2.y = fmaf(s2, wv.y, acc2.y);
        acc2.z = fmaf(s2, wv.z, acc2.z); acc2.w = fmaf(s2, wv.w, acc2.w);
        acc3.x = fmaf(s3, wv.x, acc3.x); acc3.y = fmaf(s3, wv.y, acc3.y);
        acc3.z = fmaf(s3, wv.z, acc3.z); acc3.w = fmaf(s3, wv.w, acc3.w);
        if (k < 192 && (k & 1)) {
            __stcs(&fdst[(size_t)(k >> 1) * K1_THREADS + tid], z);
        }
    }
    reinterpret_cast<float4*>(g_featW + (size_t)(row0 + 0) * HH)[lane] = acc0;
    reinterpret_cast<float4*>(g_featW + (size_t)(row0 + 1) * HH)[lane] = acc1;
    reinterpret_cast<float4*>(g_featW + (size_t)(row0 + 2) * HH)[lane] = acc2;
    reinterpret_cast<float4*>(g_featW + (size_t)(row0 + 3) * HH)[lane] = acc3;

    if (blockIdx.x == 0 && tid == 0) {
        out[OFF_BEFORE] = 64.0f;
        out[OFF_AFTER]  = 0.0f;
    }
}

// ---------------------------------------------------------------------------
// Kernel 2: WARP-PER-ROW, 2 ROWS PER WARP. grid 512 <= 592 resident capacity
// (4 blocks/SM at ~56 regs) -> the ENTIRE grid is one co-resident wave: no
// wave-quantization tail (R8 ran 1.73 waves). Per-row math is R8-identical;
// MLP constants hoisted across the two rows.
// ---------------------------------------------------------------------------
__global__ void __launch_bounds__(256) edge_kernel(const float* __restrict__ adj,
                                                   const int*   __restrict__ nbr,
                                                   const float* __restrict__ b1,
                                                   const float* __restrict__ prelu_a,
                                                   const float* __restrict__ W2,
                                                   const float* __restrict__ b2,
                                                   float* __restrict__ out) {
    __shared__ int   snbr[8][KK];
    __shared__ __align__(16) float sD[8][KK];   // D values, then reused as p1

    const int tid  = threadIdx.x;
    const int warp = tid >> 5;
    const int lane = tid & 31;

    // hoisted per-lane MLP invariants (shared by both rows)
    const int j0 = lane * 4;
    const float a0 = __ldg(&prelu_a[j0 + 0]), a1 = __ldg(&prelu_a[j0 + 1]),
                a2 = __ldg(&prelu_a[j0 + 2]), a3 = __ldg(&prelu_a[j0 + 3]);
    const float wd0 = __ldg(&W2[(j0 + 0) * 2 + 1]) - __ldg(&W2[(j0 + 0) * 2]);
    const float wd1 = __ldg(&W2[(j0 + 1) * 2 + 1]) - __ldg(&W2[(j0 + 1) * 2]);
    const float wd2 = __ldg(&W2[(j0 + 2) * 2 + 1]) - __ldg(&W2[(j0 + 2) * 2]);
    const float wd3 = __ldg(&W2[(j0 + 3) * 2 + 1]) - __ldg(&W2[(j0 + 3) * 2]);
    const float b2d = __ldg(&b2[1]) - __ldg(&b2[0]);
    const float4 bb = __ldg(&reinterpret_cast<const float4*>(b1)[lane]);

    const bool h16 = (lane & 16) != 0;
    const bool h8  = (lane & 8)  != 0;
    const bool h4  = (lane & 4)  != 0;
    const int  eidx = ((lane >> 2) & 1) * 4 + ((lane >> 3) & 1) * 2 + ((lane >> 4) & 1);
    const bool writer = (lane & 3) == 0;

    const float4* fW4 = reinterpret_cast<const float4*>(g_featW);

#pragma unroll 1
    for (int rr = 0; rr < 2; rr++) {
        const int row = blockIdx.x * 16 + rr * 8 + warp;

        const int nlo = __ldg(&nbr[row * KK + lane]);
        const int nhi = __ldg(&nbr[row * KK + lane + 32]);
        snbr[warp][lane]      = nlo;
        snbr[warp][lane + 32] = nhi;
        const float vlo = __ldcs(adj + (size_t)row * NN + nlo);
        const float vhi = __ldcs(adj + (size_t)row * NN + nhi);

        float4 fs = fW4[(size_t)row * 32 + lane];
        fs.x += bb.x; fs.y += bb.y; fs.z += bb.z; fs.w += bb.w;

        // pair_list
        {
            float2* pp = reinterpret_cast<float2*>(out + OFF_PAIR) + (long long)row * KK;
            __stcs(&pp[lane],      make_float2((float)row, (float)nlo));
            __stcs(&pp[lane + 32], make_float2((float)row, (float)nhi));
        }

        const bool dofill = (row >= K1_FILLROWS);
        float4* orow = reinterpret_cast<float4*>(out + (size_t)row * NN);
        const float4 z = make_float4(0.f, 0.f, 0.f, 0.f);

        __syncwarp();   // snbr visible (and sD from previous row fully consumed)

#pragma unroll
        for (int b = 0; b < 8; b++) {      // 8 batches of 8 edges, 8-deep gather
            float4 fd[8];
#pragma unroll
            for (int e = 0; e < 8; e++)
                fd[e] = fW4[(size_t)snbr[warp][b * 8 + e] * 32 + lane];

            // pipelined fill: 4KB while the gathers are in flight
            if (dofill) {
#pragma unroll
                for (int s = 0; s < 8; s++)
                    __stcs(&orow[(b * 8 + s) * 32 + lane], z);
            }

            float dd[8];
#pragma unroll
            for (int e = 0; e < 8; e++) {
                float h0 = fs.x - fd[e].x, h1 = fs.y - fd[e].y;
                float h2 = fs.z - fd[e].z, h3 = fs.w - fd[e].w;
                h0 = (h0 >= 0.f) ? h0 : a0 * h0;
                h1 = (h1 >= 0.f) ? h1 : a1 * h1;
                h2 = (h2 >= 0.f) ? h2 : a2 * h2;
                h3 = (h3 >= 0.f) ? h3 : a3 * h3;
                dd[e] = h0 * wd0 + h1 * wd1 + h2 * wd2 + h3 * wd3;
            }

            // selection multi-reduce (same summation tree as butterfly)
            float w[4];
#pragma unroll
            for (int i = 0; i < 4; i++) {
                float send = h16 ? dd[2 * i] : dd[2 * i + 1];
                float recv = __shfl_xor_sync(0xffffffffu, send, 16);
                w[i] = (h16 ? dd[2 * i + 1] : dd[2 * i]) + recv;
            }
            float x0, x1;
            {
                float send = h8 ? w[0] : w[1];
                float recv = __shfl_xor_sync(0xffffffffu, send, 8);
                x0 = (h8 ? w[1] : w[0]) + recv;
                send = h8 ? w[2] : w[3];
                recv = __shfl_xor_sync(0xffffffffu, send, 8);
                x1 = (h8 ? w[3] : w[2]) + recv;
            }
            float y;
            {
                float send = h4 ? x0 : x1;
                float recv = __shfl_xor_sync(0xffffffffu, send, 4);
                y = (h4 ? x1 : x0) + recv;
            }
            y += __shfl_xor_sync(0xffffffffu, y, 2);
            y += __shfl_xor_sync(0xffffffffu, y, 1);

            if (writer) sD[warp][b * 8 + eidx] = y;
        }
        __syncwarp();

        // sigmoid probs (p0 = sigmoid(-D) = e * p1)
        const float D_lo = sD[warp][lane]      + b2d;
        const float D_hi = sD[warp][lane + 32] + b2d;
        const float e_lo = expf(-D_lo), e_hi = expf(-D_hi);
        const float p1_lo = 1.0f / (1.0f + e_lo);
        const float p1_hi = 1.0f / (1.0f + e_hi);
        const float p0_lo = e_lo * p1_lo;
        const float p0_hi = e_hi * p1_hi;
        {
            float2* pr = reinterpret_cast<float2*>(out + OFF_PROB) + (long long)row * KK;
            __stcs(&pr[lane],      make_float2(p0_lo, p1_lo));
            __stcs(&pr[lane + 32], make_float2(p0_hi, p1_hi));
        }
        sD[warp][lane]      = p1_lo;    // reuse as sp1 (own-slot rewrite, safe)
        sD[warp][lane + 32] = p1_hi;
        __syncwarp();

        // stable ascending rank, vectorized (16 x LDS.128)
        int rank_lo = 0, rank_hi = 0;
        const float4* sp4 = reinterpret_cast<const float4*>(&sD[warp][0]);
#pragma unroll
        for (int q = 0; q < 16; q++) {
            float4 v = sp4[q];
            const int j = q * 4;
            rank_lo += (v.x < p1_lo) || (v.x == p1_lo && (j + 0) < lane);
            rank_lo += (v.y < p1_lo) || (v.y == p1_lo && (j + 1) < lane);
            rank_lo += (v.z < p1_lo) || (v.z == p1_lo && (j + 2) < lane);
            rank_lo += (v.w < p1_lo) || (v.w == p1_lo && (j + 3) < lane);
            rank_hi += (v.x < p1_hi) || (v.x == p1_hi && (j + 0) < lane + 32);
            rank_hi += (v.y < p1_hi) || (v.y == p1_hi && (j + 1) < lane + 32);
            rank_hi += (v.z < p1_hi) || (v.z == p1_hi && (j + 2) < lane + 32);
            rank_hi += (v.w < p1_hi) || (v.w == p1_hi && (j + 3) < lane + 32);
        }
        const int keep_lo = rank_lo >= 32;
        const int keep_hi = rank_hi >= 32;

        if (keep_lo)
            __stcs(&out[OFF_LEFT + (long long)row * 32 + (rank_lo - 32)],
                   (float)(row * KK + lane));
        if (keep_hi)
            __stcs(&out[OFF_LEFT + (long long)row * 32 + (rank_hi - 32)],
                   (float)(row * KK + lane + 32));

        // degree + nonzero-kept count
        float v = (keep_lo ? vlo : 0.f) + (keep_hi ? vhi : 0.f);
        float c = (keep_lo && vlo != 0.f ? 1.f : 0.f) +
                  (keep_hi && vhi != 0.f ? 1.f : 0.f);
#pragma unroll
        for (int off = 16; off; off >>= 1) {
            v += __shfl_xor_sync(0xffffffffu, v, off);
            c += __shfl_xor_sync(0xffffffffu, c, off);
        }
        if (lane == 0) atomicAdd(out + OFF_AFTER, c * (1.0f / 8192.0f));

        __syncwarp();   // order own-row zero-fill before scatter

        const float inv = 1.0f / (v + 1e-6f);
        if (keep_lo) __stcs(&out[(size_t)row * NN + nlo], vlo * inv);
        if (keep_hi) __stcs(&out[(size_t)row * NN + nhi], vhi * inv);
    }
}

// ---------------------------------------------------------------------------
extern "C" void kernel_launch(void* const* d_in, const int* in_sizes, int n_in,
                              void* d_out, int out_size) {
    const float* adj = nullptr; const float* feat = nullptr;
    const int*   nbr = nullptr; const float* W1   = nullptr;
    const float* b1  = nullptr; const float* pa   = nullptr;
    const float* W2  = nullptr; const float* b2   = nullptr;

    for (int i = 0; i < n_in; i++) {
        long long s = in_sizes[i];
        if      (s == (long long)NN * NN) adj  = (const float*)d_in[i];
        else if (s == (long long)NN * DD) feat = (const float*)d_in[i];
        else if (s == (long long)NN * KK) nbr  = (const int*)d_in[i];
        else if (s == (long long)DD * HH) W1   = (const float*)d_in[i];
        else if (s == HH) { if (!b1) b1 = (const float*)d_in[i];
                            else     pa = (const float*)d_in[i]; }
        else if (s == HH * 2) W2 = (const float*)d_in[i];
        else if (s == 2)      b2 = (const float*)d_in[i];
    }

    float* out = (float*)d_out;
    const int k1_smem_bytes = (DD * HH + 16 * 4 * DD) * (int)sizeof(float); // 192 KB
    static int attr_done = 0;
    if (!attr_done) {
        cudaFuncSetAttribute(featw_kernel,
                             cudaFuncAttributeMaxDynamicSharedMemorySize, k1_smem_bytes);
        attr_done = 1;
    }
    featw_kernel<<<K1_BLOCKS, K1_THREADS, k1_smem_bytes>>>(feat, W1, out);
    edge_kernel<<<NN / 16, 256>>>(adj, nbr, b1, pa, W2, b2, out);
}

// round 13
// speedup vs baseline: 1.4037x; 1.2500x over previous
#include <cuda_runtime.h>

#define NN 8192
#define KK 64
#define DD 256
#define HH 128
#define K1_BLOCKS   128
#define K1_THREADS  512
#define K1_FILLROWS 3072   // rows [0,3072) filled by k1 (24 rows/block, 96 MB)

// ---- flat fp32 output layout (concat of reference tuple) ----
#define OFF_ADJ    0LL
#define OFF_FEAT   ((long long)NN * NN)
#define OFF_PROB   (OFF_FEAT + (long long)NN * DD)
#define OFF_PAIR   (OFF_PROB + (long long)NN * KK * 2)
#define OFF_BEFORE (OFF_PAIR + (long long)NN * KK * 2)
#define OFF_AFTER  (OFF_BEFORE + 1)
#define OFF_LEFT   (OFF_AFTER + 1)

// scratch: featW = feat @ W1   [N, 128]  (4 MB, L2-resident for edge gather)
__device__ float g_featW[(size_t)NN * HH];

// ---------------------------------------------------------------------------
// Kernel 1 (R8-identical, measured 32us): featW = feat @ W1 with the 96MB
// zero-fill software-pipelined into the FMA loop. W1 staged in 128KB smem.
// ---------------------------------------------------------------------------
extern __shared__ float k1_smem[];

__global__ void __launch_bounds__(K1_THREADS) featw_kernel(const float* __restrict__ feat,
                                                           const float* __restrict__ W1,
                                                           float* __restrict__ out) {
    float* sW   = k1_smem;                  // 256*128 floats = 128 KB
    float* srow = k1_smem + DD * HH;        // 16 warps * 4 rows * 256 = 64 KB

    const int tid  = threadIdx.x;
    const int warp = tid >> 5;
    const int lane = tid & 31;

    {
        const float4* W14 = reinterpret_cast<const float4*>(W1);
        float4* sW4 = reinterpret_cast<float4*>(sW);
#pragma unroll
        for (int i = 0; i < 16; i++)
            sW4[i * K1_THREADS + tid] = W14[i * K1_THREADS + tid];
    }

    const int row0 = blockIdx.x * 64 + warp * 4;
    float* rbase = srow + warp * 4 * DD;
#pragma unroll
    for (int r = 0; r < 4; r++) {
        const float4* f4 = reinterpret_cast<const float4*>(feat + (size_t)(row0 + r) * DD);
        float4 x0 = __ldcs(&f4[lane]), x1 = __ldcs(&f4[lane + 32]);
        reinterpret_cast<float4*>(rbase + r * DD)[lane]      = x0;
        reinterpret_cast<float4*>(rbase + r * DD)[lane + 32] = x1;
        float4* oc = reinterpret_cast<float4*>(out + OFF_FEAT + (size_t)(row0 + r) * DD);
        __stcs(&oc[lane], x0); __stcs(&oc[lane + 32], x1);
    }
    __syncthreads();

    const float4* sW4 = reinterpret_cast<const float4*>(sW);
    const float* r0 = rbase;
    const float* r1 = rbase + DD;
    const float* r2 = rbase + 2 * DD;
    const float* r3 = rbase + 3 * DD;

    float4* fdst = reinterpret_cast<float4*>(
        out + (size_t)blockIdx.x * (K1_FILLROWS / K1_BLOCKS) * NN);
    const float4 z = make_float4(0.f, 0.f, 0.f, 0.f);

    float4 acc0 = make_float4(0.f, 0.f, 0.f, 0.f);
    float4 acc1 = make_float4(0.f, 0.f, 0.f, 0.f);
    float4 acc2 = make_float4(0.f, 0.f, 0.f, 0.f);
    float4 acc3 = make_float4(0.f, 0.f, 0.f, 0.f);
#pragma unroll 4
    for (int k = 0; k < DD; k++) {
        float4 wv = sW4[k * 32 + lane];
        float s0 = r0[k], s1 = r1[k], s2 = r2[k], s3 = r3[k];
        acc0.x = fmaf(s0, wv.x, acc0.x); acc0.y = fmaf(s0, wv.y, acc0.y);
        acc0.z = fmaf(s0, wv.z, acc0.z); acc0.w = fmaf(s0, wv.w, acc0.w);
        acc1.x = fmaf(s1, wv.x, acc1.x); acc1.y = fmaf(s1, wv.y, acc1.y);
        acc1.z = fmaf(s1, wv.z, acc1.z); acc1.w = fmaf(s1, wv.w, acc1.w);
        acc2.x = fmaf(s2, wv.x, acc2.x); acc2.y = fmaf(s2, wv.y, acc2.y);
        acc2.z = fmaf(s2, wv.z, acc2.z); acc2.w = fmaf(s2, wv.w, acc2.w);
        acc3.x = fmaf(s3, wv.x, acc3.x); acc3.y = fmaf(s3, wv.y, acc3.y);
        acc3.z = fmaf(s3, wv.z, acc3.z); acc3.w = fmaf(s3, wv.w, acc3.w);
        if (k < 192 && (k & 1)) {
            __stcs(&fdst[(size_t)(k >> 1) * K1_THREADS + tid], z);
        }
    }
    reinterpret_cast<float4*>(g_featW + (size_t)(row0 + 0) * HH)[lane] = acc0;
    reinterpret_cast<float4*>(g_featW + (size_t)(row0 + 1) * HH)[lane] = acc1;
    reinterpret_cast<float4*>(g_featW + (size_t)(row0 + 2) * HH)[lane] = acc2;
    reinterpret_cast<float4*>(g_featW + (size_t)(row0 + 3) * HH)[lane] = acc3;

    if (blockIdx.x == 0 && tid == 0) {
        out[OFF_BEFORE] = 64.0f;
        out[OFF_AFTER]  = 0.0f;
    }
}

// ---------------------------------------------------------------------------
// Kernel 2: WARP-PAIR-PER-ROW. 8 warps/block = 4 rows/block, grid 2048.
// Warp h of a pair handles edges [32h, 32h+32): 4 batches of 8 (half the
// serial path of R8), same per-edge D reduction tree -> p1/rank bitwise
// identical to R8. Cross-half sync via named barriers (bar.sync id,64).
// ---------------------------------------------------------------------------
__global__ void __launch_bounds__(256) edge_kernel(const float* __restrict__ adj,
                                                   const int*   __restrict__ nbr,
                                                   const float* __restrict__ b1,
                                                   const float* __restrict__ prelu_a,
                                                   const float* __restrict__ W2,
                                                   const float* __restrict__ b2,
                                                   float* __restrict__ out) {
    __shared__ int   snbr[4][KK];
    __shared__ __align__(16) float sD[4][KK];   // D values, then reused as p1
    __shared__ float2 spart[4][2];              // (deg, cnt) partial per half

    const int tid  = threadIdx.x;
    const int warp = tid >> 5;
    const int lane = tid & 31;
    const int rid  = warp & 3;        // row within block
    const int half = warp >> 2;       // 0: edges 0-31, 1: edges 32-63
    const int ebase = half * 32;
    const int row  = blockIdx.x * 4 + rid;

    // own 32 edges: neighbor + adj value
    const int mycol = __ldg(&nbr[row * KK + ebase + lane]);
    snbr[rid][ebase + lane] = mycol;
    const float myval = __ldcs(adj + (size_t)row * NN + mycol);

    const float4* fW4 = reinterpret_cast<const float4*>(g_featW);
    float4 fs = fW4[(size_t)row * 32 + lane];
    {
        float4 bb = __ldg(&reinterpret_cast<const float4*>(b1)[lane]);
        fs.x += bb.x; fs.y += bb.y; fs.z += bb.z; fs.w += bb.w;
    }

    // pair_list (own 32 edges, coalesced)
    {
        float2* pp = reinterpret_cast<float2*>(out + OFF_PAIR) + (long long)row * KK;
        __stcs(&pp[ebase + lane], make_float2((float)row, (float)mycol));
    }

    const int j0 = lane * 4;
    const float a0 = __ldg(&prelu_a[j0 + 0]), a1 = __ldg(&prelu_a[j0 + 1]),
                a2 = __ldg(&prelu_a[j0 + 2]), a3 = __ldg(&prelu_a[j0 + 3]);
    const float wd0 = __ldg(&W2[(j0 + 0) * 2 + 1]) - __ldg(&W2[(j0 + 0) * 2]);
    const float wd1 = __ldg(&W2[(j0 + 1) * 2 + 1]) - __ldg(&W2[(j0 + 1) * 2]);
    const float wd2 = __ldg(&W2[(j0 + 2) * 2 + 1]) - __ldg(&W2[(j0 + 2) * 2]);
    const float wd3 = __ldg(&W2[(j0 + 3) * 2 + 1]) - __ldg(&W2[(j0 + 3) * 2]);
    const float b2d = __ldg(&b2[1]) - __ldg(&b2[0]);

    const bool h16 = (lane & 16) != 0;
    const bool h8  = (lane & 8)  != 0;
    const bool h4  = (lane & 4)  != 0;
    const int  eidx = ((lane >> 2) & 1) * 4 + ((lane >> 3) & 1) * 2 + ((lane >> 4) & 1);
    const bool writer = (lane & 3) == 0;

    const bool dofill = (row >= K1_FILLROWS);
    float4* orow = reinterpret_cast<float4*>(out + (size_t)row * NN);
    const float4 z = make_float4(0.f, 0.f, 0.f, 0.f);

    __syncwarp();   // own snbr half visible to own warp

#pragma unroll
    for (int b = 0; b < 4; b++) {      // 4 batches of 8 edges, 8-deep gather
        float4 fd[8];
#pragma unroll
        for (int e = 0; e < 8; e++)
            fd[e] = fW4[(size_t)snbr[rid][ebase + b * 8 + e] * 32 + lane];

        // pipelined fill: this half's 8 chunks (4KB) in the gather shadow
        if (dofill) {
#pragma unroll
            for (int s = 0; s < 8; s++)
                __stcs(&orow[(ebase + b * 8 + s) * 32 + lane], z);
        }

        float dd[8];
#pragma unroll
        for (int e = 0; e < 8; e++) {
            float h0 = fs.x - fd[e].x, h1 = fs.y - fd[e].y;
            float h2 = fs.z - fd[e].z, h3 = fs.w - fd[e].w;
            h0 = (h0 >= 0.f) ? h0 : a0 * h0;
            h1 = (h1 >= 0.f) ? h1 : a1 * h1;
            h2 = (h2 >= 0.f) ? h2 : a2 * h2;
            h3 = (h3 >= 0.f) ? h3 : a3 * h3;
            dd[e] = h0 * wd0 + h1 * wd1 + h2 * wd2 + h3 * wd3;
        }

        // selection multi-reduce (same per-edge summation tree as R8)
        float w[4];
#pragma unroll
        for (int i = 0; i < 4; i++) {
            float send = h16 ? dd[2 * i] : dd[2 * i + 1];
            float recv = __shfl_xor_sync(0xffffffffu, send, 16);
            w[i] = (h16 ? dd[2 * i + 1] : dd[2 * i]) + recv;
        }
        float x0, x1;
        {
            float send = h8 ? w[0] : w[1];
            float recv = __shfl_xor_sync(0xffffffffu, send, 8);
            x0 = (h8 ? w[1] : w[0]) + recv;
            send = h8 ? w[2] : w[3];
            recv = __shfl_xor_sync(0xffffffffu, send, 8);
            x1 = (h8 ? w[3] : w[2]) + recv;
        }
        float y;
        {
            float send = h4 ? x0 : x1;
            float recv = __shfl_xor_sync(0xffffffffu, send, 4);
            y = (h4 ? x1 : x0) + recv;
        }
        y += __shfl_xor_sync(0xffffffffu, y, 2);
        y += __shfl_xor_sync(0xffffffffu, y, 1);

        if (writer) sD[rid][ebase + b * 8 + eidx] = y;
    }
    __syncwarp();

    // sigmoid probs for own edge (p0 = sigmoid(-D) = e * p1); bitwise == R8
    const float D  = sD[rid][ebase + lane] + b2d;
    const float ex = expf(-D);
    const float p1 = 1.0f / (1.0f + ex);
    const float p0 = ex * p1;
    {
        float2* pr = reinterpret_cast<float2*>(out + OFF_PROB) + (long long)row * KK;
        __stcs(&pr[ebase + lane], make_float2(p0, p1));
    }
    sD[rid][ebase + lane] = p1;       // reuse as sp1 (own-slot rewrite)

    // cross-half: both halves' p1 must be visible before rank
    asm volatile("bar.sync %0, 64;" :: "r"(1 + rid) : "memory");

    // stable ascending rank over all 64 (vectorized, 16 x LDS.128)
    int rank = 0;
    const int myidx = ebase + lane;
    const float4* sp4 = reinterpret_cast<const float4*>(&sD[rid][0]);
#pragma unroll
    for (int q = 0; q < 16; q++) {
        float4 v = sp4[q];
        const int j = q * 4;
        rank += (v.x < p1) || (v.x == p1 && (j + 0) < myidx);
        rank += (v.y < p1) || (v.y == p1 && (j + 1) < myidx);
        rank += (v.z < p1) || (v.z == p1 && (j + 2) < myidx);
        rank += (v.w < p1) || (v.w == p1 && (j + 3) < myidx);
    }
    const int keep = rank >= 32;

    if (keep)
        __stcs(&out[OFF_LEFT + (long long)row * 32 + (rank - 32)],
               (float)(row * KK + myidx));

    // degree + nonzero-kept partials for this half
    float v = keep ? myval : 0.f;
    float c = (keep && myval != 0.f) ? 1.f : 0.f;
#pragma unroll
    for (int off = 16; off; off >>= 1) {
        v += __shfl_xor_sync(0xffffffffu, v, off);
        c += __shfl_xor_sync(0xffffffffu, c, off);
    }
    if (lane == 0) spart[rid][half] = make_float2(v, c);

    // order: fill stores + partials before cross-half scatter/combine
    __threadfence_block();
    asm volatile("bar.sync %0, 64;" :: "r"(1 + rid) : "memory");

    const float2 pA = spart[rid][0];
    const float2 pB = spart[rid][1];
    const float vtot = pA.x + pB.x;
    if (half == 0 && lane == 0)
        atomicAdd(out + OFF_AFTER, (pA.y + pB.y) * (1.0f / 8192.0f));

    const float inv = 1.0f / (vtot + 1e-6f);
    if (keep) __stcs(&out[(size_t)row * NN + mycol], myval * inv);
}

// ---------------------------------------------------------------------------
extern "C" void kernel_launch(void* const* d_in, const int* in_sizes, int n_in,
                              void* d_out, int out_size) {
    const float* adj = nullptr; const float* feat = nullptr;
    const int*   nbr = nullptr; const float* W1   = nullptr;
    const float* b1  = nullptr; const float* pa   = nullptr;
    const float* W2  = nullptr; const float* b2   = nullptr;

    for (int i = 0; i < n_in; i++) {
        long long s = in_sizes[i];
        if      (s == (long long)NN * NN) adj  = (const float*)d_in[i];
        else if (s == (long long)NN * DD) feat = (const float*)d_in[i];
        else if (s == (long long)NN * KK) nbr  = (const int*)d_in[i];
        else if (s == (long long)DD * HH) W1   = (const float*)d_in[i];
        else if (s == HH) { if (!b1) b1 = (const float*)d_in[i];
                            else     pa = (const float*)d_in[i]; }
        else if (s == HH * 2) W2 = (const float*)d_in[i];
        else if (s == 2)      b2 = (const float*)d_in[i];
    }

    float* out = (float*)d_out;
    const int k1_smem_bytes = (DD * HH + 16 * 4 * DD) * (int)sizeof(float); // 192 KB
    static int attr_done = 0;
    if (!attr_done) {
        cudaFuncSetAttribute(featw_kernel,
                             cudaFuncAttributeMaxDynamicSharedMemorySize, k1_smem_bytes);
        attr_done = 1;
    }
    featw_kernel<<<K1_BLOCKS, K1_THREADS, k1_smem_bytes>>>(feat, W1, out);
    edge_kernel<<<NN / 4, 256>>>(adj, nbr, b1, pa, W2, b2, out);
}

// round 14
// speedup vs baseline: 1.4090x; 1.0038x over previous
#include <cuda_runtime.h>

#define NN 8192
#define KK 64
#define DD 256
#define HH 128
#define K1_BLOCKS   128
#define K1_THREADS  512
#define K1_FILLROWS 3072   // rows [0,3072) filled by k1 (24 rows/block, 96 MB)

// ---- flat fp32 output layout (concat of reference tuple) ----
#define OFF_ADJ    0LL
#define OFF_FEAT   ((long long)NN * NN)
#define OFF_PROB   (OFF_FEAT + (long long)NN * DD)
#define OFF_PAIR   (OFF_PROB + (long long)NN * KK * 2)
#define OFF_BEFORE (OFF_PAIR + (long long)NN * KK * 2)
#define OFF_AFTER  (OFF_BEFORE + 1)
#define OFF_LEFT   (OFF_AFTER + 1)

// scratch: featW = feat @ W1   [N, 128]  (4 MB, L2-resident for edge gather)
__device__ float g_featW[(size_t)NN * HH];

// ---------------------------------------------------------------------------
// Kernel 1: featW = feat @ W1 + 96MB pipelined zero-fill (R8 structure).
// CHANGE vs R13: scalar row values loaded as float4 broadcasts (4 LDS.128
// per 4 k-iters instead of 16 scalar LDS) -> smem no longer co-binds with
// the FMA pipe. Fill store schedule byte-identical to R8/R13.
// ---------------------------------------------------------------------------
extern __shared__ float k1_smem[];

__global__ void __launch_bounds__(K1_THREADS) featw_kernel(const float* __restrict__ feat,
                                                           const float* __restrict__ W1,
                                                           float* __restrict__ out) {
    float* sW   = k1_smem;                  // 256*128 floats = 128 KB
    float* srow = k1_smem + DD * HH;        // 16 warps * 4 rows * 256 = 64 KB

    const int tid  = threadIdx.x;
    const int warp = tid >> 5;
    const int lane = tid & 31;

    {
        const float4* W14 = reinterpret_cast<const float4*>(W1);
        float4* sW4 = reinterpret_cast<float4*>(sW);
#pragma unroll
        for (int i = 0; i < 16; i++)
            sW4[i * K1_THREADS + tid] = W14[i * K1_THREADS + tid];
    }

    const int row0 = blockIdx.x * 64 + warp * 4;
    float* rbase = srow + warp * 4 * DD;
#pragma unroll
    for (int r = 0; r < 4; r++) {
        const float4* f4 = reinterpret_cast<const float4*>(feat + (size_t)(row0 + r) * DD);
        float4 x0 = __ldcs(&f4[lane]), x1 = __ldcs(&f4[lane + 32]);
        reinterpret_cast<float4*>(rbase + r * DD)[lane]      = x0;
        reinterpret_cast<float4*>(rbase + r * DD)[lane + 32] = x1;
        float4* oc = reinterpret_cast<float4*>(out + OFF_FEAT + (size_t)(row0 + r) * DD);
        __stcs(&oc[lane], x0); __stcs(&oc[lane + 32], x1);
    }
    __syncthreads();

    const float4* sW4 = reinterpret_cast<const float4*>(sW);
    const float4* r0v = reinterpret_cast<const float4*>(rbase);
    const float4* r1v = reinterpret_cast<const float4*>(rbase + DD);
    const float4* r2v = reinterpret_cast<const float4*>(rbase + 2 * DD);
    const float4* r3v = reinterpret_cast<const float4*>(rbase + 3 * DD);

    float4* fdst = reinterpret_cast<float4*>(
        out + (size_t)blockIdx.x * (K1_FILLROWS / K1_BLOCKS) * NN);
    const float4 z = make_float4(0.f, 0.f, 0.f, 0.f);

    float4 acc0 = make_float4(0.f, 0.f, 0.f, 0.f);
    float4 acc1 = make_float4(0.f, 0.f, 0.f, 0.f);
    float4 acc2 = make_float4(0.f, 0.f, 0.f, 0.f);
    float4 acc3 = make_float4(0.f, 0.f, 0.f, 0.f);
#pragma unroll 2
    for (int k4 = 0; k4 < DD / 4; k4++) {
        const float4 v0 = r0v[k4], v1 = r1v[k4], v2 = r2v[k4], v3 = r3v[k4];
#pragma unroll
        for (int j = 0; j < 4; j++) {
            const int k = k4 * 4 + j;
            float4 wv = sW4[k * 32 + lane];
            const float s0 = j == 0 ? v0.x : j == 1 ? v0.y : j == 2 ? v0.z : v0.w;
            const float s1 = j == 0 ? v1.x : j == 1 ? v1.y : j == 2 ? v1.z : v1.w;
            const float s2 = j == 0 ? v2.x : j == 1 ? v2.y : j == 2 ? v2.z : v2.w;
            const float s3 = j == 0 ? v3.x : j == 1 ? v3.y : j == 2 ? v3.z : v3.w;
            acc0.x = fmaf(s0, wv.x, acc0.x); acc0.y = fmaf(s0, wv.y, acc0.y);
            acc0.z = fmaf(s0, wv.z, acc0.z); acc0.w = fmaf(s0, wv.w, acc0.w);
            acc1.x = fmaf(s1, wv.x, acc1.x); acc1.y = fmaf(s1, wv.y, acc1.y);
            acc1.z = fmaf(s1, wv.z, acc1.z); acc1.w = fmaf(s1, wv.w, acc1.w);
            acc2.x = fmaf(s2, wv.x, acc2.x); acc2.y = fmaf(s2, wv.y, acc2.y);
            acc2.z = fmaf(s2, wv.z, acc2.z); acc2.w = fmaf(s2, wv.w, acc2.w);
            acc3.x = fmaf(s3, wv.x, acc3.x); acc3.y = fmaf(s3, wv.y, acc3.y);
            acc3.z = fmaf(s3, wv.z, acc3.z); acc3.w = fmaf(s3, wv.w, acc3.w);
            if (k < 192 && (k & 1)) {
                __stcs(&fdst[(size_t)(k >> 1) * K1_THREADS + tid], z);
            }
        }
    }
    reinterpret_cast<float4*>(g_featW + (size_t)(row0 + 0) * HH)[lane] = acc0;
    reinterpret_cast<float4*>(g_featW + (size_t)(row0 + 1) * HH)[lane] = acc1;
    reinterpret_cast<float4*>(g_featW + (size_t)(row0 + 2) * HH)[lane] = acc2;
    reinterpret_cast<float4*>(g_featW + (size_t)(row0 + 3) * HH)[lane] = acc3;

    if (blockIdx.x == 0 && tid == 0) {
        out[OFF_BEFORE] = 64.0f;
        out[OFF_AFTER]  = 0.0f;
    }
}

// ---------------------------------------------------------------------------
// Kernel 2: ONE ROW = ONE 64-THREAD BLOCK (warp pair), grid 8192.
// Math/stores bit-identical to R13; named barriers replaced by __syncthreads
// (2-warp block). ~21 blocks/SM resident -> finest-grain latency hiding.
// ---------------------------------------------------------------------------
__global__ void __launch_bounds__(64) edge_kernel(const float* __restrict__ adj,
                                                  const int*   __restrict__ nbr,
                                                  const float* __restrict__ b1,
                                                  const float* __restrict__ prelu_a,
                                                  const float* __restrict__ W2,
                                                  const float* __restrict__ b2,
                                                  float* __restrict__ out) {
    __shared__ int   snbr[KK];
    __shared__ __align__(16) float sD[KK];   // D values, then reused as p1
    __shared__ float2 spart[2];              // (deg, cnt) partial per half

    const int tid  = threadIdx.x;
    const int half = tid >> 5;        // 0: edges 0-31, 1: edges 32-63
    const int lane = tid & 31;
    const int ebase = half * 32;
    const int row  = blockIdx.x;

    // own 32 edges: neighbor + adj value
    const int mycol = __ldg(&nbr[row * KK + ebase + lane]);
    snbr[ebase + lane] = mycol;
    const float myval = __ldcs(adj + (size_t)row * NN + mycol);

    const float4* fW4 = reinterpret_cast<const float4*>(g_featW);
    float4 fs = fW4[(size_t)row * 32 + lane];
    {
        float4 bb = __ldg(&reinterpret_cast<const float4*>(b1)[lane]);
        fs.x += bb.x; fs.y += bb.y; fs.z += bb.z; fs.w += bb.w;
    }

    // pair_list (own 32 edges, coalesced)
    {
        float2* pp = reinterpret_cast<float2*>(out + OFF_PAIR) + (long long)row * KK;
        __stcs(&pp[ebase + lane], make_float2((float)row, (float)mycol));
    }

    const int j0 = lane * 4;
    const float a0 = __ldg(&prelu_a[j0 + 0]), a1 = __ldg(&prelu_a[j0 + 1]),
                a2 = __ldg(&prelu_a[j0 + 2]), a3 = __ldg(&prelu_a[j0 + 3]);
    const float wd0 = __ldg(&W2[(j0 + 0) * 2 + 1]) - __ldg(&W2[(j0 + 0) * 2]);
    const float wd1 = __ldg(&W2[(j0 + 1) * 2 + 1]) - __ldg(&W2[(j0 + 1) * 2]);
    const float wd2 = __ldg(&W2[(j0 + 2) * 2 + 1]) - __ldg(&W2[(j0 + 2) * 2]);
    const float wd3 = __ldg(&W2[(j0 + 3) * 2 + 1]) - __ldg(&W2[(j0 + 3) * 2]);
    const float b2d = __ldg(&b2[1]) - __ldg(&b2[0]);

    const bool h16 = (lane & 16) != 0;
    const bool h8  = (lane & 8)  != 0;
    const bool h4  = (lane & 4)  != 0;
    const int  eidx = ((lane >> 2) & 1) * 4 + ((lane >> 3) & 1) * 2 + ((lane >> 4) & 1);
    const bool writer = (lane & 3) == 0;

    const bool dofill = (row >= K1_FILLROWS);
    float4* orow = reinterpret_cast<float4*>(out + (size_t)row * NN);
    const float4 z = make_float4(0.f, 0.f, 0.f, 0.f);

    __syncwarp();   // own snbr half visible to own warp

#pragma unroll
    for (int b = 0; b < 4; b++) {      // 4 batches of 8 edges, 8-deep gather
        float4 fd[8];
#pragma unroll
        for (int e = 0; e < 8; e++)
            fd[e] = fW4[(size_t)snbr[ebase + b * 8 + e] * 32 + lane];

        // pipelined fill: this half's 8 chunks (4KB) in the gather shadow
        if (dofill) {
#pragma unroll
            for (int s = 0; s < 8; s++)
                __stcs(&orow[(ebase + b * 8 + s) * 32 + lane], z);
        }

        float dd[8];
#pragma unroll
        for (int e = 0; e < 8; e++) {
            float h0 = fs.x - fd[e].x, h1 = fs.y - fd[e].y;
            float h2 = fs.z - fd[e].z, h3 = fs.w - fd[e].w;
            h0 = (h0 >= 0.f) ? h0 : a0 * h0;
            h1 = (h1 >= 0.f) ? h1 : a1 * h1;
            h2 = (h2 >= 0.f) ? h2 : a2 * h2;
            h3 = (h3 >= 0.f) ? h3 : a3 * h3;
            dd[e] = h0 * wd0 + h1 * wd1 + h2 * wd2 + h3 * wd3;
        }

        // selection multi-reduce (same per-edge summation tree as R8/R13)
        float w[4];
#pragma unroll
        for (int i = 0; i < 4; i++) {
            float send = h16 ? dd[2 * i] : dd[2 * i + 1];
            float recv = __shfl_xor_sync(0xffffffffu, send, 16);
            w[i] = (h16 ? dd[2 * i + 1] : dd[2 * i]) + recv;
        }
        float x0, x1;
        {
            float send = h8 ? w[0] : w[1];
            float recv = __shfl_xor_sync(0xffffffffu, send, 8);
            x0 = (h8 ? w[1] : w[0]) + recv;
            send = h8 ? w[2] : w[3];
            recv = __shfl_xor_sync(0xffffffffu, send, 8);
            x1 = (h8 ? w[3] : w[2]) + recv;
        }
        float y;
        {
            float send = h4 ? x0 : x1;
            float recv = __shfl_xor_sync(0xffffffffu, send, 4);
            y = (h4 ? x1 : x0) + recv;
        }
        y += __shfl_xor_sync(0xffffffffu, y, 2);
        y += __shfl_xor_sync(0xffffffffu, y, 1);

        if (writer) sD[ebase + b * 8 + eidx] = y;
    }
    __syncwarp();

    // sigmoid probs for own edge (p0 = sigmoid(-D) = e * p1); bitwise == R13
    const float D  = sD[ebase + lane] + b2d;
    const float ex = expf(-D);
    const float p1 = 1.0f / (1.0f + ex);
    const float p0 = ex * p1;
    {
        float2* pr = reinterpret_cast<float2*>(out + OFF_PROB) + (long long)row * KK;
        __stcs(&pr[ebase + lane], make_float2(p0, p1));
    }
    sD[ebase + lane] = p1;            // reuse as sp1 (own-slot rewrite)

    __syncthreads();                  // both halves' p1 visible

    // stable ascending rank over all 64 (vectorized, 16 x LDS.128)
    int rank = 0;
    const int myidx = ebase + lane;
    const float4* sp4 = reinterpret_cast<const float4*>(sD);
#pragma unroll
    for (int q = 0; q < 16; q++) {
        float4 v = sp4[q];
        const int j = q * 4;
        rank += (v.x < p1) || (v.x == p1 && (j + 0) < myidx);
        rank += (v.y < p1) || (v.y == p1 && (j + 1) < myidx);
        rank += (v.z < p1) || (v.z == p1 && (j + 2) < myidx);
        rank += (v.w < p1) || (v.w == p1 && (j + 3) < myidx);
    }
    const int keep = rank >= 32;

    if (keep)
        __stcs(&out[OFF_LEFT + (long long)row * 32 + (rank - 32)],
               (float)(row * KK + myidx));

    // degree + nonzero-kept partials for this half
    float v = keep ? myval : 0.f;
    float c = (keep && myval != 0.f) ? 1.f : 0.f;
#pragma unroll
    for (int off = 16; off; off >>= 1) {
        v += __shfl_xor_sync(0xffffffffu, v, off);
        c += __shfl_xor_sync(0xffffffffu, c, off);
    }
    if (lane == 0) spart[half] = make_float2(v, c);

    // order fill stores + partials before cross-half scatter/combine
    __syncthreads();

    const float2 pA = spart[0];
    const float2 pB = spart[1];
    const float vtot = pA.x + pB.x;
    if (half == 0 && lane == 0)
        atomicAdd(out + OFF_AFTER, (pA.y + pB.y) * (1.0f / 8192.0f));

    const float inv = 1.0f / (vtot + 1e-6f);
    if (keep) __stcs(&out[(size_t)row * NN + mycol], myval * inv);
}

// ---------------------------------------------------------------------------
extern "C" void kernel_launch(void* const* d_in, const int* in_sizes, int n_in,
                              void* d_out, int out_size) {
    const float* adj = nullptr; const float* feat = nullptr;
    const int*   nbr = nullptr; const float* W1   = nullptr;
    const float* b1  = nullptr; const float* pa   = nullptr;
    const float* W2  = nullptr; const float* b2   = nullptr;

    for (int i = 0; i < n_in; i++) {
        long long s = in_sizes[i];
        if      (s == (long long)NN * NN) adj  = (const float*)d_in[i];
        else if (s == (long long)NN * DD) feat = (const float*)d_in[i];
        else if (s == (long long)NN * KK) nbr  = (const int*)d_in[i];
        else if (s == (long long)DD * HH) W1   = (const float*)d_in[i];
        else if (s == HH) { if (!b1) b1 = (const float*)d_in[i];
                            else     pa = (const float*)d_in[i]; }
        else if (s == HH * 2) W2 = (const float*)d_in[i];
        else if (s == 2)      b2 = (const float*)d_in[i];
    }

    float* out = (float*)d_out;
    const int k1_smem_bytes = (DD * HH + 16 * 4 * DD) * (int)sizeof(float); // 192 KB
    static int attr_done = 0;
    if (!attr_done) {
        cudaFuncSetAttribute(featw_kernel,
                             cudaFuncAttributeMaxDynamicSharedMemorySize, k1_smem_bytes);
        attr_done = 1;
    }
    featw_kernel<<<K1_BLOCKS, K1_THREADS, k1_smem_bytes>>>(feat, W1, out);
    edge_kernel<<<NN, 64>>>(adj, nbr, b1, pa, W2, b2, out);
}